// round 3
// baseline (speedup 1.0000x reference)
#include <cuda_runtime.h>
#include <cuda_bf16.h>

// Correlation layer (FlowNet-style), MAX_DISP=4.
// first, second: (B=4, C=256, H=128, W=224) fp32 NCHW
// out: (B, 81, H, W) fp32, out[b, dy*9+dx, y, x] =
//      (1/C) * sum_c first[b,c,y,x] * second[b,c,y+dy-4,x+dx-4]   (0 outside)
//
// Tiling:
//   block = (x-tile of 56, 4 y-rows, 1 batch)
//   threads = (14 x-groups, 9 dy, 4 local-y) = 504
//   each thread: 4 consecutive x pixels, one dy, 9 dx -> 36 accumulators
//   channels processed in chunks of 8 through shared memory.

#define B_   4
#define C_   256
#define H_   128
#define W_   224
#define P_   4
#define D_   9      // 2P+1
#define ND_  81

#define TX    56    // x-tile width (224 = 4*56)
#define YT    4     // y rows per block
#define XPT   4     // x pixels per thread
#define XT    14    // x-thread count (56/4)
#define CC    8     // channels per smem chunk

#define SWID  64    // second tile width incl. halo (56+8)
#define SROW  68    // padded smem row stride for second (breaks bank aliasing)
#define SH    12    // second rows incl. halo (4+8)
#define FROW  56    // first smem row stride

#define NTHR  (XT * D_ * YT)   // 504

__global__ __launch_bounds__(NTHR, 1)
void corr_kernel(const float* __restrict__ first,
                 const float* __restrict__ second,
                 float* __restrict__ out)
{
    __shared__ float s_s[CC][SH * SROW];   // 8 * 816 * 4B = 26112 B
    __shared__ float f_s[CC][YT * FROW];   // 8 * 224 * 4B =  7168 B

    const int xt = blockIdx.x;          // 0..3
    const int y0 = blockIdx.y * YT;     // 0..124
    const int b  = blockIdx.z;          // 0..3
    const int x0 = xt * TX;

    const int tx = threadIdx.x;         // 0..13  (x-group)
    const int dy = threadIdx.y;         // 0..8
    const int ly = threadIdx.z;         // 0..3
    const int tid = tx + XT * (dy + D_ * ly);

    float acc[XPT][D_];
#pragma unroll
    for (int i = 0; i < XPT; i++)
#pragma unroll
        for (int d = 0; d < D_; d++)
            acc[i][d] = 0.0f;

    const long f_base = ((long)b * C_) * H_ * W_;
    const long s_base = f_base;

    for (int c0 = 0; c0 < C_; c0 += CC) {
        // ---- load first tile: CC channels x YT rows x 56 cols ----
        for (int idx = tid; idx < CC * YT * FROW; idx += NTHR) {
            int c   = idx / (YT * FROW);
            int rem = idx - c * (YT * FROW);
            int r   = rem / FROW;
            int xx  = rem - r * FROW;
            f_s[c][rem] = first[f_base + (long)(c0 + c) * (H_ * W_)
                                + (y0 + r) * W_ + (x0 + xx)];
        }
        // ---- load second tile: CC channels x 12 rows x 64 cols (zero-padded) ----
        for (int idx = tid; idx < CC * SH * SWID; idx += NTHR) {
            int c   = idx / (SH * SWID);
            int rem = idx - c * (SH * SWID);
            int r   = rem / SWID;
            int xx  = rem - r * SWID;
            int gy  = y0 - P_ + r;
            int gx  = x0 - P_ + xx;
            float v = 0.0f;
            if ((unsigned)gy < (unsigned)H_ && (unsigned)gx < (unsigned)W_)
                v = second[s_base + (long)(c0 + c) * (H_ * W_) + gy * W_ + gx];
            s_s[c][r * SROW + xx] = v;
        }
        __syncthreads();

        // ---- accumulate ----
#pragma unroll
        for (int c = 0; c < CC; c++) {
            const float4 f4 = *(const float4*)&f_s[c][ly * FROW + tx * XPT];
            const float* srow = &s_s[c][(ly + dy) * SROW + tx * XPT];
            float w[12];
            *(float4*)&w[0] = *(const float4*)&srow[0];
            *(float4*)&w[4] = *(const float4*)&srow[4];
            *(float4*)&w[8] = *(const float4*)&srow[8];
            const float f0 = f4.x, f1 = f4.y, f2 = f4.z, f3 = f4.w;
#pragma unroll
            for (int d = 0; d < D_; d++) {
                acc[0][d] += f0 * w[0 + d];
                acc[1][d] += f1 * w[1 + d];
                acc[2][d] += f2 * w[2 + d];
                acc[3][d] += f3 * w[3 + d];
            }
        }
        __syncthreads();
    }

    // ---- store: 9 float4 per thread ----
    const float scale = 1.0f / (float)C_;
    const int y = y0 + ly;
    const int xo = x0 + tx * XPT;
#pragma unroll
    for (int d = 0; d < D_; d++) {
        const int ch = dy * D_ + d;
        float4 o;
        o.x = acc[0][d] * scale;
        o.y = acc[1][d] * scale;
        o.z = acc[2][d] * scale;
        o.w = acc[3][d] * scale;
        *(float4*)&out[(((long)b * ND_ + ch) * H_ + y) * W_ + xo] = o;
    }
}

extern "C" void kernel_launch(void* const* d_in, const int* in_sizes, int n_in,
                              void* d_out, int out_size)
{
    const float* first  = (const float*)d_in[0];
    const float* second = (const float*)d_in[1];
    float* out = (float*)d_out;

    dim3 grid(W_ / TX, H_ / YT, B_);   // (4, 32, 4)
    dim3 block(XT, D_, YT);            // (14, 9, 4) = 504
    corr_kernel<<<grid, block>>>(first, second, out);
}

// round 4
// speedup vs baseline: 2.8499x; 2.8499x over previous
#include <cuda_runtime.h>
#include <cuda_bf16.h>
#include <cstdint>

// Correlation layer (FlowNet-style), MAX_DISP=4.
// first, second: (B=4, C=256, H=128, W=224) fp32 NCHW
// out: (B, 81, H, W) fp32
//
// R4: cp.async double-buffered pipeline + precomputed slot addressing.

#define B_   4
#define C_   256
#define H_   128
#define W_   224
#define P_   4
#define D_   9      // 2P+1
#define ND_  81

#define TX    56    // x-tile width (224 = 4*56)
#define YT    4     // y rows per block
#define XPT   4     // x pixels per thread
#define XT    14    // x-thread count (56/4)
#define CC    8     // channels per smem chunk
#define NCHUNK (C_ / CC)   // 32

#define SWID  64    // second tile width incl. halo (56+8)
#define SROW  68    // padded smem row stride (floats) for second
#define SH    12    // second rows incl. halo (4+8)
#define FROW  56    // first smem row stride (floats)

#define SCH   (SH * SROW)        // 816 floats per channel (second)
#define FCH   (YT * FROW)        // 224 floats per channel (first)
#define SBUF_FLOATS (CC * SCH)   // 6528
#define FBUF_FLOATS (CC * FCH)   // 1792
#define SBUF_BYTES  (SBUF_FLOATS * 4)   // 26112
#define FBUF_BYTES  (FBUF_FLOATS * 4)   // 7168
#define SMEM_TOTAL  (2 * SBUF_BYTES + 2 * FBUF_BYTES)  // 66560

#define S_F4_PER_CH   (SH * (SWID / 4))          // 192 float4 per channel
#define S_F4_TOTAL    (CC * S_F4_PER_CH)         // 1536
#define F_F4_TOTAL    (CC * YT * (FROW / 4))     // 448

#define NTHR  (XT * D_ * YT)   // 504
#define CHUNK_STRIDE_B ((size_t)CC * H_ * W_ * 4)   // bytes per 8-channel step

__device__ __forceinline__ void cp16(uint32_t dst, const float* src, int sz) {
    asm volatile("cp.async.cg.shared.global [%0], [%1], 16, %2;\n"
                 :: "r"(dst), "l"(src), "r"(sz));
}
__device__ __forceinline__ void cp_commit() {
    asm volatile("cp.async.commit_group;\n");
}
__device__ __forceinline__ void cp_wait1() {
    asm volatile("cp.async.wait_group 1;\n");
}

__global__ __launch_bounds__(NTHR, 1)
void corr_kernel(const float* __restrict__ first,
                 const float* __restrict__ second,
                 float* __restrict__ out)
{
    extern __shared__ float dyn[];
    // layout: [0 .. 2*6528)       second buffers (buf0, buf1)
    //         [13056 .. +2*1792)  first buffers  (buf0, buf1)
    float* sbase = dyn;
    float* fbase = dyn + 2 * SBUF_FLOATS;

    const int xt = blockIdx.x;          // 0..3
    const int y0 = blockIdx.y * YT;     // 0..124
    const int b  = blockIdx.z;          // 0..3
    const int x0 = xt * TX;

    const int tx = threadIdx.x;         // 0..13
    const int dy = threadIdx.y;         // 0..8
    const int ly = threadIdx.z;         // 0..3
    const int tid = tx + XT * (dy + D_ * ly);

    const float* img_base = first  + (size_t)b * C_ * H_ * W_;
    const float* sec_base = second + (size_t)b * C_ * H_ * W_;

    // ---- precompute second-tile cp.async slots (4 per thread max) ----
    const float* sp[4];
    uint32_t     sdst[4];
    int          ssz[4];
    bool         sact[4];
#pragma unroll
    for (int j = 0; j < 4; j++) {
        int pos = tid + j * NTHR;
        sact[j] = (pos < S_F4_TOTAL);
        int p   = sact[j] ? pos : 0;
        int c   = p / S_F4_PER_CH;
        int rem = p - c * S_F4_PER_CH;
        int r   = rem >> 4;           // /16
        int xq  = rem & 15;
        int gy  = y0 - P_ + r;
        int gxs = x0 - P_ + xq * 4;   // float4 start; fully in or fully out
        bool valid = ((unsigned)gy < (unsigned)H_) && ((unsigned)gxs < (unsigned)(W_ - 3));
        ssz[j] = valid ? 16 : 0;
        sp[j]  = sec_base + ((size_t)c * H_ * W_ + (valid ? (gy * W_ + gxs) : 0));
        sdst[j] = (uint32_t)__cvta_generic_to_shared(
                      &sbase[c * SCH + r * SROW + xq * 4]);
    }
    // ---- precompute first-tile slot (1 per thread for tid<448) ----
    const bool fact = (tid < F_F4_TOTAL);
    int ft  = fact ? tid : 0;
    int fc  = ft / (YT * (FROW / 4));            // /56
    int frm = ft - fc * (YT * (FROW / 4));
    int fr  = frm / (FROW / 4);                  // /14
    int fxq = frm - fr * (FROW / 4);
    const float* fp = img_base + ((size_t)fc * H_ * W_ + (y0 + fr) * W_ + x0 + fxq * 4);
    uint32_t fdst = (uint32_t)__cvta_generic_to_shared(
                        &fbase[fc * FCH + fr * FROW + fxq * 4]);

    float acc[XPT][D_];
#pragma unroll
    for (int i = 0; i < XPT; i++)
#pragma unroll
        for (int d = 0; d < D_; d++)
            acc[i][d] = 0.0f;

    // ---- prefetch chunk 0 into buf 0 ----
    {
#pragma unroll
        for (int j = 0; j < 4; j++)
            if (sact[j]) cp16(sdst[j], sp[j], ssz[j]);
        if (fact) cp16(fdst, fp, 16);
        cp_commit();
    }

    const int s_ro = (ly + dy) * SROW + tx * XPT;   // per-thread second read offset
    const int f_ro = ly * FROW + tx * XPT;          // per-thread first read offset

    for (int k = 0; k < NCHUNK; k++) {
        // prefetch k+1 into the other buffer
        if (k + 1 < NCHUNK) {
            const size_t coff = (size_t)(k + 1) * (CC * H_ * W_);
            const uint32_t db = ((k + 1) & 1) ? SBUF_BYTES : 0;
            const uint32_t fb = ((k + 1) & 1) ? FBUF_BYTES : 0;
#pragma unroll
            for (int j = 0; j < 4; j++)
                if (sact[j]) cp16(sdst[j] + db, sp[j] + coff, ssz[j]);
            if (fact) cp16(fdst + fb, fp + coff, 16);
        }
        cp_commit();
        cp_wait1();           // chunk k resident
        __syncthreads();

        const float* sb = sbase + (k & 1) * SBUF_FLOATS + s_ro;
        const float* fbp = fbase + (k & 1) * FBUF_FLOATS + f_ro;

#pragma unroll
        for (int c = 0; c < CC; c++) {
            const float4 f4 = *(const float4*)(fbp + c * FCH);
            const float* srow = sb + c * SCH;
            float w[12];
            *(float4*)&w[0] = *(const float4*)&srow[0];
            *(float4*)&w[4] = *(const float4*)&srow[4];
            *(float4*)&w[8] = *(const float4*)&srow[8];
            const float f0 = f4.x, f1 = f4.y, f2 = f4.z, f3 = f4.w;
#pragma unroll
            for (int d = 0; d < D_; d++) {
                acc[0][d] += f0 * w[0 + d];
                acc[1][d] += f1 * w[1 + d];
                acc[2][d] += f2 * w[2 + d];
                acc[3][d] += f3 * w[3 + d];
            }
        }
        __syncthreads();      // protect buffer (k&1) before it is refilled at k+2
    }

    // ---- store: 9 float4 per thread ----
    const float scale = 1.0f / (float)C_;
    const int y = y0 + ly;
    const int xo = x0 + tx * XPT;
#pragma unroll
    for (int d = 0; d < D_; d++) {
        const int ch = dy * D_ + d;
        float4 o;
        o.x = acc[0][d] * scale;
        o.y = acc[1][d] * scale;
        o.z = acc[2][d] * scale;
        o.w = acc[3][d] * scale;
        *(float4*)&out[(((size_t)b * ND_ + ch) * H_ + y) * W_ + xo] = o;
    }
}

extern "C" void kernel_launch(void* const* d_in, const int* in_sizes, int n_in,
                              void* d_out, int out_size)
{
    const float* first  = (const float*)d_in[0];
    const float* second = (const float*)d_in[1];
    float* out = (float*)d_out;

    cudaFuncSetAttribute(corr_kernel,
                         cudaFuncAttributeMaxDynamicSharedMemorySize, SMEM_TOTAL);

    dim3 grid(W_ / TX, H_ / YT, B_);   // (4, 32, 4)
    dim3 block(XT, D_, YT);            // (14, 9, 4) = 504
    corr_kernel<<<grid, block, SMEM_TOTAL>>>(first, second, out);
}